// round 5
// baseline (speedup 1.0000x reference)
#include <cuda_runtime.h>
#include <math.h>

#define POOLED   7
#define CHANNELS 256
#define BATCH    4
#define H        50
#define W        50
#define HW       (H*W)
#define SCALE    0.0625f

// NHWC scratch: featT[b][h][w][c]
__device__ float g_featT[(size_t)BATCH * HW * CHANNELS];

// ---------------- Transpose NCHW -> NHWC (tiled, conflict-free) -------------
__global__ void __launch_bounds__(256)
transpose_kernel(const float* __restrict__ feat)
{
    __shared__ float tile[32][33];

    int b   = blockIdx.z;
    int hw0 = blockIdx.x * 32;
    int c0  = blockIdx.y * 32;
    int tx  = threadIdx.x;   // 0..31
    int ty  = threadIdx.y;   // 0..7

    const float* in = feat + (size_t)b * CHANNELS * HW;

    #pragma unroll
    for (int i = 0; i < 32; i += 8) {
        int c  = c0 + ty + i;
        int hw = hw0 + tx;
        if (hw < HW)
            tile[ty + i][tx] = in[(size_t)c * HW + hw];
    }
    __syncthreads();

    float* outp = g_featT + (size_t)b * HW * CHANNELS;
    #pragma unroll
    for (int i = 0; i < 32; i += 8) {
        int hw = hw0 + ty + i;
        int c  = c0 + tx;
        if (hw < HW)
            outp[(size_t)hw * CHANNELS + c] = tile[tx][ty + i];
    }
}

// ---------------- RoI max-pool: block = (roi, ph), thread = 2 channels ------
__global__ void __launch_bounds__(128)
roipool_kernel2(const float* __restrict__ rois,
                float* __restrict__ out)
{
    __shared__ float s[POOLED][CHANNELS];   // [pw][c]

    int blk = blockIdx.x;          // r*7 + ph
    int r   = blk / POOLED;
    int ph  = blk - r * POOLED;
    int t   = threadIdx.x;         // 0..127, channels 2t, 2t+1

    const float* roi = rois + r * 5;
    int   b  = (int)roi[0];
    float x1 = floorf(__fadd_rn(__fmul_rn(roi[1], SCALE), 0.5f));
    float y1 = floorf(__fadd_rn(__fmul_rn(roi[2], SCALE), 0.5f));
    float x2 = floorf(__fadd_rn(__fmul_rn(roi[3], SCALE), 0.5f));
    float y2 = floorf(__fadd_rn(__fmul_rn(roi[4], SCALE), 0.5f));

    float roi_w = fmaxf(__fadd_rn(__fadd_rn(x2, -x1), 1.0f), 1.0f);
    float roi_h = fmaxf(__fadd_rn(__fadd_rn(y2, -y1), 1.0f), 1.0f);

    // Match XLA-CPU fast-math: x/7 lowered to x * fl32(1/7)
    const float inv7 = 1.0f / 7.0f;
    float bin_w = __fmul_rn(roi_w, inv7);
    float bin_h = __fmul_rn(roi_h, inv7);

    float phf = (float)ph;
    float hs = fminf(fmaxf(__fadd_rn(floorf(__fmul_rn(phf, bin_h)), y1), 0.0f), (float)H);
    float he = fminf(fmaxf(__fadd_rn(ceilf(__fmul_rn(__fadd_rn(phf, 1.0f), bin_h)), y1), 0.0f), (float)H);
    int ihs = (int)hs, ihe = (int)he;
    bool hempty = (ihe <= ihs);

    const float2* base = (const float2*)(g_featT + (size_t)b * HW * CHANNELS) + t;
    // float2 units: pixel (h,w) lives at (h*W + w)*128 + t

    #pragma unroll
    for (int pw = 0; pw < POOLED; ++pw) {
        float pwf = (float)pw;
        float ws = fminf(fmaxf(__fadd_rn(floorf(__fmul_rn(pwf, bin_w)), x1), 0.0f), (float)W);
        float we = fminf(fmaxf(__fadd_rn(ceilf(__fmul_rn(__fadd_rn(pwf, 1.0f), bin_w)), x1), 0.0f), (float)W);
        int iws = (int)ws, iwe = (int)we;
        bool empty = hempty || (iwe <= iws);

        float2 m = make_float2(-INFINITY, -INFINITY);
        if (!empty) {
            for (int h = ihs; h < ihe; ++h) {
                const float2* rowp = base + (size_t)(h * W) * 128;
                int wlast = iwe - 1;
                for (int w0 = iws; w0 < iwe; w0 += 4) {
                    // 4 independent loads (clamped) issued before any consume
                    int w1 = min(w0 + 1, wlast);
                    int w2 = min(w0 + 2, wlast);
                    int w3 = min(w0 + 3, wlast);
                    float2 a = __ldg(rowp + (size_t)w0 * 128);
                    float2 bb = __ldg(rowp + (size_t)w1 * 128);
                    float2 cc = __ldg(rowp + (size_t)w2 * 128);
                    float2 dd = __ldg(rowp + (size_t)w3 * 128);
                    float mx0 = fmaxf(fmaxf(a.x, bb.x), fmaxf(cc.x, dd.x));
                    float my0 = fmaxf(fmaxf(a.y, bb.y), fmaxf(cc.y, dd.y));
                    m.x = fmaxf(m.x, mx0);
                    m.y = fmaxf(m.y, my0);
                }
            }
        } else {
            m.x = 0.0f; m.y = 0.0f;
        }
        s[pw][2 * t]     = m.x;
        s[pw][2 * t + 1] = m.y;
    }
    __syncthreads();

    // Cooperative store: consecutive lanes -> consecutive (c,pw) pairs.
    // out[((r*256 + c)*7 + ph)*7 + pw] = r*12544 + c*49 + ph*7 + pw
    float* ob = out + (size_t)r * 12544 + ph * 7;
    #pragma unroll
    for (int j = t; j < CHANNELS * POOLED; j += 128) {
        int c  = j / POOLED;
        int pw = j - c * POOLED;
        ob[c * 49 + pw] = s[pw][c];
    }
}

extern "C" void kernel_launch(void* const* d_in, const int* in_sizes, int n_in,
                              void* d_out, int out_size)
{
    const float* feat = (const float*)d_in[0];
    const float* rois = (const float*)d_in[1];
    float* out = (float*)d_out;

    dim3 tgrid((HW + 31) / 32, CHANNELS / 32, BATCH);   // 79 x 8 x 4
    dim3 tblk(32, 8);
    transpose_kernel<<<tgrid, tblk>>>(feat);

    int blocks = 128 * POOLED;   // (roi, ph) = 896
    roipool_kernel2<<<blocks, 128>>>(rois, out);
}

// round 6
// speedup vs baseline: 1.4930x; 1.4930x over previous
#include <cuda_runtime.h>
#include <math.h>

#define POOLED   7
#define CHANNELS 256
#define BATCH    4
#define H        50
#define W        50
#define HW       (H*W)
#define SCALE    0.0625f

// NHWC scratch: featT[b][h][w][c]
__device__ float g_featT[(size_t)BATCH * HW * CHANNELS];

// ---------------- Transpose NCHW -> NHWC (tiled, conflict-free) -------------
__global__ void __launch_bounds__(256)
transpose_kernel(const float* __restrict__ feat)
{
    __shared__ float tile[32][33];

    int b   = blockIdx.z;
    int hw0 = blockIdx.x * 32;
    int c0  = blockIdx.y * 32;
    int tx  = threadIdx.x;   // 0..31
    int ty  = threadIdx.y;   // 0..7

    const float* in = feat + (size_t)b * CHANNELS * HW;

    #pragma unroll
    for (int i = 0; i < 32; i += 8) {
        int c  = c0 + ty + i;
        int hw = hw0 + tx;
        if (hw < HW)
            tile[ty + i][tx] = in[(size_t)c * HW + hw];
    }
    __syncthreads();

    float* outp = g_featT + (size_t)b * HW * CHANNELS;
    #pragma unroll
    for (int i = 0; i < 32; i += 8) {
        int hw = hw0 + ty + i;
        int c  = c0 + tx;
        if (hw < HW)
            outp[(size_t)hw * CHANNELS + c] = tile[tx][ty + i];
    }
}

// ------------- RoI max-pool: block = (roi, bin), thread = 2 channels --------
__global__ void __launch_bounds__(128)
roipool_kernel3(const float* __restrict__ rois,
                float* __restrict__ out)
{
    int blk = blockIdx.x;          // r*49 + bin
    int r   = blk / 49;
    int bin = blk - r * 49;
    int ph  = bin / POOLED;
    int pw  = bin - ph * POOLED;
    int t   = threadIdx.x;         // 0..127 -> channels 2t, 2t+1

    const float* roi = rois + r * 5;
    int   b  = (int)roi[0];
    float x1 = floorf(__fadd_rn(__fmul_rn(roi[1], SCALE), 0.5f));
    float y1 = floorf(__fadd_rn(__fmul_rn(roi[2], SCALE), 0.5f));
    float x2 = floorf(__fadd_rn(__fmul_rn(roi[3], SCALE), 0.5f));
    float y2 = floorf(__fadd_rn(__fmul_rn(roi[4], SCALE), 0.5f));

    float roi_w = fmaxf(__fadd_rn(__fadd_rn(x2, -x1), 1.0f), 1.0f);
    float roi_h = fmaxf(__fadd_rn(__fadd_rn(y2, -y1), 1.0f), 1.0f);

    // Match XLA-CPU fast-math: x/7 lowered to x * fl32(1/7)
    const float inv7 = 1.0f / 7.0f;
    float bin_w = __fmul_rn(roi_w, inv7);
    float bin_h = __fmul_rn(roi_h, inv7);

    float pwf = (float)pw;
    float phf = (float)ph;

    float ws = fminf(fmaxf(__fadd_rn(floorf(__fmul_rn(pwf, bin_w)), x1), 0.0f), (float)W);
    float we = fminf(fmaxf(__fadd_rn(ceilf(__fmul_rn(__fadd_rn(pwf, 1.0f), bin_w)), x1), 0.0f), (float)W);
    float hs = fminf(fmaxf(__fadd_rn(floorf(__fmul_rn(phf, bin_h)), y1), 0.0f), (float)H);
    float he = fminf(fmaxf(__fadd_rn(ceilf(__fmul_rn(__fadd_rn(phf, 1.0f), bin_h)), y1), 0.0f), (float)H);

    int iws = (int)ws, iwe = (int)we;
    int ihs = (int)hs, ihe = (int)he;

    // out index: ((r*256 + c)*49 + bin), c = 2t and 2t+1
    float* o = out + (size_t)r * 12544 + (size_t)(2 * t) * 49 + bin;

    if (ihe <= ihs || iwe <= iws) {
        o[0]  = 0.0f;
        o[49] = 0.0f;
        return;
    }

    int bw = iwe - iws;                 // bin width (uniform across block)
    int n  = (ihe - ihs) * bw;          // pixel count (uniform across block)

    const float2* base = (const float2*)(g_featT + (size_t)b * HW * CHANNELS) + t;
    // float2 units per pixel: 128; pixel (h,w) at offset (h*W + w)*128

    float2 m = make_float2(-INFINITY, -INFINITY);
    int nlast = n - 1;
    for (int p0 = 0; p0 < n; p0 += 4) {
        // 4 independent clamped pixel indices -> 4 in-flight LDG.64
        int p1 = min(p0 + 1, nlast);
        int p2 = min(p0 + 2, nlast);
        int p3 = min(p0 + 3, nlast);

        int h0 = p0 / bw, w0 = p0 - h0 * bw;
        int h1 = p1 / bw, w1 = p1 - h1 * bw;
        int h2 = p2 / bw, w2 = p2 - h2 * bw;
        int h3 = p3 / bw, w3 = p3 - h3 * bw;

        float2 a = __ldg(base + (size_t)((ihs + h0) * W + iws + w0) * 128);
        float2 bb = __ldg(base + (size_t)((ihs + h1) * W + iws + w1) * 128);
        float2 cc = __ldg(base + (size_t)((ihs + h2) * W + iws + w2) * 128);
        float2 dd = __ldg(base + (size_t)((ihs + h3) * W + iws + w3) * 128);

        m.x = fmaxf(m.x, fmaxf(fmaxf(a.x, bb.x), fmaxf(cc.x, dd.x)));
        m.y = fmaxf(m.y, fmaxf(fmaxf(a.y, bb.y), fmaxf(cc.y, dd.y)));
    }

    o[0]  = m.x;
    o[49] = m.y;
}

extern "C" void kernel_launch(void* const* d_in, const int* in_sizes, int n_in,
                              void* d_out, int out_size)
{
    const float* feat = (const float*)d_in[0];
    const float* rois = (const float*)d_in[1];
    float* out = (float*)d_out;

    dim3 tgrid((HW + 31) / 32, CHANNELS / 32, BATCH);   // 79 x 8 x 4
    dim3 tblk(32, 8);
    transpose_kernel<<<tgrid, tblk>>>(feat);

    int blocks = 128 * 49;   // (roi, bin) = 6272
    roipool_kernel3<<<blocks, 128>>>(rois, out);
}

// round 7
// speedup vs baseline: 1.7912x; 1.1997x over previous
#include <cuda_runtime.h>
#include <math.h>

#define POOLED   7
#define CHANNELS 256
#define BATCH    4
#define H        50
#define W        50
#define HW       (H*W)
#define SCALE    0.0625f

// NHWC scratch: featT[b][h][w][c]
__device__ float g_featT[(size_t)BATCH * HW * CHANNELS];

// ---------------- Transpose NCHW -> NHWC (tiled, conflict-free) -------------
__global__ void __launch_bounds__(256)
transpose_kernel(const float* __restrict__ feat)
{
    __shared__ float tile[32][33];

    int b   = blockIdx.z;
    int hw0 = blockIdx.x * 32;
    int c0  = blockIdx.y * 32;
    int tx  = threadIdx.x;   // 0..31
    int ty  = threadIdx.y;   // 0..7

    const float* in = feat + (size_t)b * CHANNELS * HW;

    #pragma unroll
    for (int i = 0; i < 32; i += 8) {
        int c  = c0 + ty + i;
        int hw = hw0 + tx;
        if (hw < HW)
            tile[ty + i][tx] = in[(size_t)c * HW + hw];
    }
    __syncthreads();

    float* outp = g_featT + (size_t)b * HW * CHANNELS;
    #pragma unroll
    for (int i = 0; i < 32; i += 8) {
        int hw = hw0 + ty + i;
        int c  = c0 + tx;
        if (hw < HW)
            outp[(size_t)hw * CHANNELS + c] = tile[tx][ty + i];
    }
}

// ------------- RoI max-pool: block = (roi, bin), offset table in smem -------
__global__ void __launch_bounds__(128)
roipool_kernel4(const float* __restrict__ rois,
                float* __restrict__ out)
{
    __shared__ int soff[96];       // padded pixel offsets (float2 units), max 84

    int blk = blockIdx.x;          // r*49 + bin
    int r   = blk / 49;
    int bin = blk - r * 49;
    int ph  = bin / POOLED;
    int pw  = bin - ph * POOLED;
    int t   = threadIdx.x;         // 0..127 -> channels 2t, 2t+1

    const float* roi = rois + r * 5;
    int   b  = (int)roi[0];
    float x1 = floorf(__fadd_rn(__fmul_rn(roi[1], SCALE), 0.5f));
    float y1 = floorf(__fadd_rn(__fmul_rn(roi[2], SCALE), 0.5f));
    float x2 = floorf(__fadd_rn(__fmul_rn(roi[3], SCALE), 0.5f));
    float y2 = floorf(__fadd_rn(__fmul_rn(roi[4], SCALE), 0.5f));

    float roi_w = fmaxf(__fadd_rn(__fadd_rn(x2, -x1), 1.0f), 1.0f);
    float roi_h = fmaxf(__fadd_rn(__fadd_rn(y2, -y1), 1.0f), 1.0f);

    // Match XLA-CPU fast-math: x/7 lowered to x * fl32(1/7)
    const float inv7 = 1.0f / 7.0f;
    float bin_w = __fmul_rn(roi_w, inv7);
    float bin_h = __fmul_rn(roi_h, inv7);

    float pwf = (float)pw;
    float phf = (float)ph;

    float ws = fminf(fmaxf(__fadd_rn(floorf(__fmul_rn(pwf, bin_w)), x1), 0.0f), (float)W);
    float we = fminf(fmaxf(__fadd_rn(ceilf(__fmul_rn(__fadd_rn(pwf, 1.0f), bin_w)), x1), 0.0f), (float)W);
    float hs = fminf(fmaxf(__fadd_rn(floorf(__fmul_rn(phf, bin_h)), y1), 0.0f), (float)H);
    float he = fminf(fmaxf(__fadd_rn(ceilf(__fmul_rn(__fadd_rn(phf, 1.0f), bin_h)), y1), 0.0f), (float)H);

    int iws = (int)ws, iwe = (int)we;
    int ihs = (int)hs, ihe = (int)he;

    // out index: ((r*256 + c)*49 + bin), c = 2t and 2t+1
    float* o = out + (size_t)r * 12544 + (size_t)(2 * t) * 49 + bin;

    if (ihe <= ihs || iwe <= iws) {     // block-uniform
        o[0]  = 0.0f;
        o[49] = 0.0f;
        return;
    }

    int bw    = iwe - iws;                      // <= 9 after clamping
    int n     = (ihe - ihs) * bw;               // <= 81
    int n_pad = (n + 3) & ~3;                   // <= 84 < 96

    // Build offset table: one int div per participating thread, once.
    if (t < n_pad) {
        int p = min(t, n - 1);                  // pad by replicating last pixel
        int h = p / bw;
        int w = p - h * bw;
        soff[t] = ((ihs + h) * W + (iws + w)) * 128;   // float2 units
    }
    __syncthreads();

    const float2* base = (const float2*)(g_featT + (size_t)b * HW * CHANNELS) + t;

    float2 m = make_float2(-INFINITY, -INFINITY);
    for (int p = 0; p < n_pad; p += 4) {
        int4 o4 = *(const int4*)&soff[p];       // LDS.128, warp-broadcast
        float2 a  = __ldg(base + o4.x);
        float2 bb = __ldg(base + o4.y);
        float2 cc = __ldg(base + o4.z);
        float2 dd = __ldg(base + o4.w);
        m.x = fmaxf(m.x, fmaxf(fmaxf(a.x, bb.x), fmaxf(cc.x, dd.x)));
        m.y = fmaxf(m.y, fmaxf(fmaxf(a.y, bb.y), fmaxf(cc.y, dd.y)));
    }

    o[0]  = m.x;
    o[49] = m.y;
}

extern "C" void kernel_launch(void* const* d_in, const int* in_sizes, int n_in,
                              void* d_out, int out_size)
{
    const float* feat = (const float*)d_in[0];
    const float* rois = (const float*)d_in[1];
    float* out = (float*)d_out;

    dim3 tgrid((HW + 31) / 32, CHANNELS / 32, BATCH);   // 79 x 8 x 4
    dim3 tblk(32, 8);
    transpose_kernel<<<tgrid, tblk>>>(feat);

    int blocks = 128 * 49;   // (roi, bin) = 6272
    roipool_kernel4<<<blocks, 128>>>(rois, out);
}